// round 1
// baseline (speedup 1.0000x reference)
#include <cuda_runtime.h>
#include <cuda_bf16.h>

// Batch Conv1D as implicit-im2col SGEMM.
// x: [B=8, M=32, L=1024, C=256] f32   -> flattened per image: row l of A = 768
//    contiguous floats starting at l*256 (rows overlap, stride 256).
// W: [K=3, C=256, F=256] f32          -> flattened = B matrix [768 x 256] row-major.
// out: [8, 32, 1022, 256] f32.

namespace {

constexpr int L    = 1024;
constexpr int C    = 256;
constexpr int F    = 256;
constexpr int LOUT = 1022;   // L - K + 1
constexpr int KTOT = 768;    // K * C

constexpr int BM = 128;      // output positions per block
constexpr int BN = 128;      // output features per block
constexpr int BK = 16;       // k-slice
constexpr int TM = 8;
constexpr int TN = 8;
constexpr int NTHREADS = (BM / TM) * (BN / TN);  // 256
constexpr int NTILES = KTOT / BK;                // 48

__global__ __launch_bounds__(NTHREADS, 2)
void conv1d_sgemm_kernel(const float* __restrict__ x,
                         const float* __restrict__ w,
                         const float* __restrict__ bias,
                         float* __restrict__ out)
{
    __shared__ float As[2][BK][BM];
    __shared__ float Bs[2][BK][BN];

    const int img = blockIdx.z;          // 0..255  (B*M images)
    const int l0  = blockIdx.y * BM;     // output-position tile
    const int f0  = blockIdx.x * BN;     // feature tile

    const float* xb = x   + (size_t)img * (L * C);
    float*       ob = out + (size_t)img * (LOUT * F);

    const int tid = threadIdx.x;
    const int tx  = tid & 15;            // N dim (features)
    const int ty  = tid >> 4;            // M dim (positions)

    // ---- A tile load mapping: 128 rows x 16 k = 512 float4, 2 per thread ----
    const int  a_row   = tid >> 1;              // 0..127
    const int  a_k     = (tid & 1) * 8;         // 0 or 8
    const bool a_valid = (l0 + a_row) < LOUT;   // guard overlap past last valid l
    const float* a_src = xb + (size_t)(l0 + a_row) * C + a_k;

    // ---- B tile load mapping: 16 k-rows x 128 f = 512 float4, 2 per thread ----
    const int b_k = tid >> 4;                   // 0..15
    const int b_f = (tid & 15) * 4;             // 0..60
    const float* b_src = w + (size_t)b_k * F + (f0 + b_f);

    float4 ra0, ra1, rb0, rb1;

    // prologue: fetch tile 0
    {
        if (a_valid) {
            ra0 = *reinterpret_cast<const float4*>(a_src);
            ra1 = *reinterpret_cast<const float4*>(a_src + 4);
        } else {
            ra0 = make_float4(0.f, 0.f, 0.f, 0.f);
            ra1 = make_float4(0.f, 0.f, 0.f, 0.f);
        }
        rb0 = *reinterpret_cast<const float4*>(b_src);
        rb1 = *reinterpret_cast<const float4*>(b_src + 64);

        As[0][a_k + 0][a_row] = ra0.x;
        As[0][a_k + 1][a_row] = ra0.y;
        As[0][a_k + 2][a_row] = ra0.z;
        As[0][a_k + 3][a_row] = ra0.w;
        As[0][a_k + 4][a_row] = ra1.x;
        As[0][a_k + 5][a_row] = ra1.y;
        As[0][a_k + 6][a_row] = ra1.z;
        As[0][a_k + 7][a_row] = ra1.w;
        *reinterpret_cast<float4*>(&Bs[0][b_k][b_f])      = rb0;
        *reinterpret_cast<float4*>(&Bs[0][b_k][b_f + 64]) = rb1;
    }
    __syncthreads();

    float acc[TM][TN];
    #pragma unroll
    for (int i = 0; i < TM; ++i)
        #pragma unroll
        for (int j = 0; j < TN; ++j)
            acc[i][j] = 0.f;

    for (int t = 0; t < NTILES; ++t) {
        const int cur = t & 1;
        const bool more = (t + 1) < NTILES;

        // prefetch next tile into registers (overlaps with compute below)
        if (more) {
            const int kk = (t + 1) * BK;
            if (a_valid) {
                ra0 = *reinterpret_cast<const float4*>(a_src + kk);
                ra1 = *reinterpret_cast<const float4*>(a_src + kk + 4);
            } else {
                ra0 = make_float4(0.f, 0.f, 0.f, 0.f);
                ra1 = make_float4(0.f, 0.f, 0.f, 0.f);
            }
            rb0 = *reinterpret_cast<const float4*>(b_src + (size_t)kk * F);
            rb1 = *reinterpret_cast<const float4*>(b_src + (size_t)kk * F + 64);
        }

        // compute on current buffers
        #pragma unroll
        for (int k = 0; k < BK; ++k) {
            float a[TM], b[TN];
            *reinterpret_cast<float4*>(a)     = *reinterpret_cast<const float4*>(&As[cur][k][ty * TM]);
            *reinterpret_cast<float4*>(a + 4) = *reinterpret_cast<const float4*>(&As[cur][k][ty * TM + 4]);
            *reinterpret_cast<float4*>(b)     = *reinterpret_cast<const float4*>(&Bs[cur][k][tx * TN]);
            *reinterpret_cast<float4*>(b + 4) = *reinterpret_cast<const float4*>(&Bs[cur][k][tx * TN + 4]);
            #pragma unroll
            for (int i = 0; i < TM; ++i)
                #pragma unroll
                for (int j = 0; j < TN; ++j)
                    acc[i][j] += a[i] * b[j];
        }

        // stash prefetched regs into the other buffer
        if (more) {
            const int nxt = cur ^ 1;
            As[nxt][a_k + 0][a_row] = ra0.x;
            As[nxt][a_k + 1][a_row] = ra0.y;
            As[nxt][a_k + 2][a_row] = ra0.z;
            As[nxt][a_k + 3][a_row] = ra0.w;
            As[nxt][a_k + 4][a_row] = ra1.x;
            As[nxt][a_k + 5][a_row] = ra1.y;
            As[nxt][a_k + 6][a_row] = ra1.z;
            As[nxt][a_k + 7][a_row] = ra1.w;
            *reinterpret_cast<float4*>(&Bs[nxt][b_k][b_f])      = rb0;
            *reinterpret_cast<float4*>(&Bs[nxt][b_k][b_f + 64]) = rb1;
            __syncthreads();
        }
    }

    // ---- epilogue: bias add + guarded vectorized store ----
    const float* bp = bias + f0 + tx * TN;
    const float4 bv0 = *reinterpret_cast<const float4*>(bp);
    const float4 bv1 = *reinterpret_cast<const float4*>(bp + 4);

    #pragma unroll
    for (int i = 0; i < TM; ++i) {
        const int l = l0 + ty * TM + i;
        if (l < LOUT) {
            float4 v0, v1;
            v0.x = acc[i][0] + bv0.x;
            v0.y = acc[i][1] + bv0.y;
            v0.z = acc[i][2] + bv0.z;
            v0.w = acc[i][3] + bv0.w;
            v1.x = acc[i][4] + bv1.x;
            v1.y = acc[i][5] + bv1.y;
            v1.z = acc[i][6] + bv1.z;
            v1.w = acc[i][7] + bv1.w;
            float* op = ob + (size_t)l * F + f0 + tx * TN;
            *reinterpret_cast<float4*>(op)     = v0;
            *reinterpret_cast<float4*>(op + 4) = v1;
        }
    }
}

}  // namespace

extern "C" void kernel_launch(void* const* d_in, const int* in_sizes, int n_in,
                              void* d_out, int out_size)
{
    const float* x  = (const float*)d_in[0];   // [8,32,1024,256]
    const float* w  = (const float*)d_in[1];   // [3,256,256]
    const float* b  = (const float*)d_in[2];   // [256]
    float* out      = (float*)d_out;           // [8,32,1022,256]

    dim3 grid(F / BN,                      // 2 feature tiles
              (LOUT + BM - 1) / BM,        // 8 position tiles
              8 * 32);                     // 256 images
    conv1d_sgemm_kernel<<<grid, NTHREADS>>>(x, w, b, out);
}

// round 3
// speedup vs baseline: 5.0504x; 5.0504x over previous
#include <cuda_runtime.h>
#include <cuda_fp16.h>
#include <cstdint>

// Batch Conv1D as implicit-im2col GEMM using classic mma.sync (HMMA, fp16 in /
// fp32 accum). Toolchain note: harness compiles to base sm_103 PTX, so
// tcgen05/TMEM ("a"-only) is unavailable; sm_80-level tensor PTX is used.
//
// x: [256 images][1024][256] f32 -> pre-converted to fp16 g_xh.
//    im2col row l = g_xh[img][l*256 .. l*256+768) (contiguous, free im2col).
// W: [3,256,256] f32 -> fp16 g_wf16 [768][256] (k-major, f contiguous).
// GEMM per CTA: M=128 rows x N=128 feats, K=768 in 24 chunks of 32.

namespace {

constexpr int LOUT = 1022;
constexpr int KTOT = 768;
constexpr int NIT  = KTOT / 32;          // 24 k-chunks
constexpr int NTHREADS = 256;

constexpr int A_STRIDE = 80;             // bytes per A smem row (32 fp16 + pad)
constexpr int B_STRIDE = 272;            // bytes per B smem row (128 fp16 + pad)
constexpr int A_BYTES  = 128 * A_STRIDE; // 10240
constexpr int B_BYTES  = 32 * B_STRIDE;  // 8704

constexpr size_t X_ELEMS = 256u * 1024u * 256u;   // 67,108,864

__device__ __half g_wf16[KTOT * 256];
__device__ __half g_xh[X_ELEMS + 1024];  // +pad: rows 1022/1023 im2col overrun (discarded)

// ---------------- PTX helpers ----------------

__device__ __forceinline__ uint32_t smem_u32(const void* p) {
    return (uint32_t)__cvta_generic_to_shared(p);
}

__device__ __forceinline__ void cp16(uint32_t dst, const void* src) {
    asm volatile("cp.async.cg.shared.global [%0], [%1], 16;" :: "r"(dst), "l"(src));
}
__device__ __forceinline__ void cp_commit() {
    asm volatile("cp.async.commit_group;" ::: "memory");
}
__device__ __forceinline__ void cp_wait1() {
    asm volatile("cp.async.wait_group 1;" ::: "memory");
}
__device__ __forceinline__ void cp_wait0() {
    asm volatile("cp.async.wait_group 0;" ::: "memory");
}

__device__ __forceinline__ void ldsm4(uint32_t (&r)[4], uint32_t addr) {
    asm volatile("ldmatrix.sync.aligned.m8n8.x4.shared.b16 {%0,%1,%2,%3}, [%4];"
                 : "=r"(r[0]), "=r"(r[1]), "=r"(r[2]), "=r"(r[3]) : "r"(addr));
}
__device__ __forceinline__ void ldsm4t(uint32_t (&r)[4], uint32_t addr) {
    asm volatile("ldmatrix.sync.aligned.m8n8.x4.trans.shared.b16 {%0,%1,%2,%3}, [%4];"
                 : "=r"(r[0]), "=r"(r[1]), "=r"(r[2]), "=r"(r[3]) : "r"(addr));
}

__device__ __forceinline__ void mma16816(float (&c)[4], const uint32_t (&a)[4],
                                         uint32_t b0, uint32_t b1) {
    asm volatile(
        "mma.sync.aligned.m16n8k16.row.col.f32.f16.f16.f32 "
        "{%0,%1,%2,%3}, {%4,%5,%6,%7}, {%8,%9}, {%0,%1,%2,%3};"
        : "+f"(c[0]), "+f"(c[1]), "+f"(c[2]), "+f"(c[3])
        : "r"(a[0]), "r"(a[1]), "r"(a[2]), "r"(a[3]), "r"(b0), "r"(b1));
}

// ---------------- pre-pass: fp32 -> fp16 ----------------

__global__ void xconv_kernel(const float* __restrict__ x) {
    size_t i = (size_t)blockIdx.x * 256 + threadIdx.x;   // one uint4 (8 fp16) per thread
    const float4 v0 = *(const float4*)(x + i * 8);
    const float4 v1 = *(const float4*)(x + i * 8 + 4);
    __half2 h0 = __floats2half2_rn(v0.x, v0.y);
    __half2 h1 = __floats2half2_rn(v0.z, v0.w);
    __half2 h2 = __floats2half2_rn(v1.x, v1.y);
    __half2 h3 = __floats2half2_rn(v1.z, v1.w);
    uint4 p;
    p.x = *(uint32_t*)&h0; p.y = *(uint32_t*)&h1;
    p.z = *(uint32_t*)&h2; p.w = *(uint32_t*)&h3;
    *(uint4*)(g_xh + i * 8) = p;
}

__global__ void wconv_kernel(const float* __restrict__ W) {
    int i = blockIdx.x * 256 + threadIdx.x;              // 768*256 threads
    g_wf16[i] = __float2half_rn(W[i]);
}

// ---------------- main GEMM kernel ----------------

__global__ __launch_bounds__(NTHREADS, 2)
void conv1d_hmma_kernel(const float* __restrict__ bias, float* __restrict__ out)
{
    __shared__ __align__(128) uint8_t smA[2][A_BYTES];
    __shared__ __align__(128) uint8_t smB[2][B_BYTES];

    const int tid  = threadIdx.x;
    const int wid  = tid >> 5;
    const int lane = tid & 31;

    const int f0  = blockIdx.x * 128;       // feature tile
    const int l0  = blockIdx.y * 128;       // row tile
    const int img = blockIdx.z;

    const __half* xb = g_xh + (size_t)img * (1024 * 256);
    float*        ob = out  + (size_t)img * (LOUT * 256);

    // warp tile: 32 (m) x 64 (n); 4 warps along m, 2 along n
    const int wm = (wid >> 1) * 32;
    const int wn = (wid & 1) * 64;

    const uint32_t sA0 = smem_u32(&smA[0][0]);
    const uint32_t sA1 = smem_u32(&smA[1][0]);
    const uint32_t sB0 = smem_u32(&smB[0][0]);
    const uint32_t sB1 = smem_u32(&smB[1][0]);

    // cp.async source/dest mapping
    const int a_row = tid >> 1;              // 0..127
    const int a_sg  = tid & 1;               // 2 x 16B per half-row
    const __half* a_src = xb + (size_t)(l0 + a_row) * 256 + a_sg * 16;
    const uint32_t a_dst = a_row * A_STRIDE + a_sg * 32;

    const int b_row = tid >> 3;              // 0..31
    const int b_cg  = tid & 7;               // 8 x 32B along f
    const __half* b_src = g_wf16 + (size_t)b_row * 256 + f0 + b_cg * 16;
    const uint32_t b_dst = b_row * B_STRIDE + b_cg * 32;

    // ldmatrix lane base offsets
    const uint32_t a_lane = (uint32_t)(wm + (lane & 15)) * A_STRIDE + (lane >> 4) * 16;
    const uint32_t b_lane = (uint32_t)(lane & 15) * B_STRIDE
                          + (uint32_t)(wn + (lane >> 4) * 8) * 2;

    float acc[2][8][4];
    #pragma unroll
    for (int mt = 0; mt < 2; ++mt)
        #pragma unroll
        for (int nt = 0; nt < 8; ++nt)
            #pragma unroll
            for (int q = 0; q < 4; ++q)
                acc[mt][nt][q] = 0.f;

    // prologue: stage 0
    {
        cp16(sA0 + a_dst,      a_src);
        cp16(sA0 + a_dst + 16, a_src + 8);
        cp16(sB0 + b_dst,      b_src);
        cp16(sB0 + b_dst + 16, b_src + 8);
        cp_commit();
    }

    for (int t = 0; t < NIT; ++t) {
        const uint32_t sA = (t & 1) ? sA1 : sA0;
        const uint32_t sB = (t & 1) ? sB1 : sB0;

        if (t + 1 < NIT) {
            const uint32_t nA = (t & 1) ? sA0 : sA1;
            const uint32_t nB = (t & 1) ? sB0 : sB1;
            const __half* asrc = a_src + (t + 1) * 32;
            const __half* bsrc = b_src + (size_t)(t + 1) * 32 * 256;
            cp16(nA + a_dst,      asrc);
            cp16(nA + a_dst + 16, asrc + 8);
            cp16(nB + b_dst,      bsrc);
            cp16(nB + b_dst + 16, bsrc + 8);
            cp_commit();
            cp_wait1();
        } else {
            cp_wait0();
        }
        __syncthreads();

        #pragma unroll
        for (int ks = 0; ks < 2; ++ks) {
            uint32_t af[2][4];
            ldsm4(af[0], sA + a_lane + ks * 32);
            ldsm4(af[1], sA + a_lane + 16 * A_STRIDE + ks * 32);
            uint32_t bf[4][4];
            #pragma unroll
            for (int n2 = 0; n2 < 4; ++n2)
                ldsm4t(bf[n2], sB + b_lane + ks * (16 * B_STRIDE) + n2 * 32);
            #pragma unroll
            for (int mt = 0; mt < 2; ++mt)
                #pragma unroll
                for (int n2 = 0; n2 < 4; ++n2) {
                    mma16816(acc[mt][2 * n2],     af[mt], bf[n2][0], bf[n2][1]);
                    mma16816(acc[mt][2 * n2 + 1], af[mt], bf[n2][2], bf[n2][3]);
                }
        }
        __syncthreads();
    }

    // ---- epilogue: bias + guarded store straight from registers ----
    const int g  = lane >> 2;
    const int tq = lane & 3;
    #pragma unroll
    for (int nt = 0; nt < 8; ++nt) {
        const int col = f0 + wn + nt * 8 + tq * 2;
        const float b0 = __ldg(bias + col);
        const float b1 = __ldg(bias + col + 1);
        #pragma unroll
        for (int mt = 0; mt < 2; ++mt) {
            const int r = l0 + wm + mt * 16 + g;
            if (r < LOUT) {
                float2 v = make_float2(acc[mt][nt][0] + b0, acc[mt][nt][1] + b1);
                *(float2*)(ob + (size_t)r * 256 + col) = v;
            }
            if (r + 8 < LOUT) {
                float2 v = make_float2(acc[mt][nt][2] + b0, acc[mt][nt][3] + b1);
                *(float2*)(ob + (size_t)(r + 8) * 256 + col) = v;
            }
        }
    }
}

}  // namespace

extern "C" void kernel_launch(void* const* d_in, const int* in_sizes, int n_in,
                              void* d_out, int out_size)
{
    const float* x  = (const float*)d_in[0];   // [8,32,1024,256]
    const float* w  = (const float*)d_in[1];   // [3,256,256]
    const float* b  = (const float*)d_in[2];   // [256]
    float* out      = (float*)d_out;           // [8,32,1022,256]

    // pre-pass: fp32 -> fp16 staging
    xconv_kernel<<<(int)(X_ELEMS / 8 / 256), 256>>>(x);   // 32768 blocks
    wconv_kernel<<<KTOT, 256>>>(w);

    dim3 grid(2, 8, 256);                      // f-tiles, m-tiles, images
    conv1d_hmma_kernel<<<grid, NTHREADS>>>(b, out);
}